// round 9
// baseline (speedup 1.0000x reference)
#include <cuda_runtime.h>
#include <cuda_fp16.h>
#include <stdint.h>
#include <math.h>

#define BSZ 512
#define TIN 128
#define FDIM 64
#define UNITS 1024
#define OUT_STEPS 32
#define NSTEPS 159           // TIN + OUT_STEPS - 1 LSTM steps
#define NGATE 4096           // 4*UNITS, gate-interleaved: n' = u*4 + g
#define KTOT 1088            // 1024 (h) + 64 (x)
#define KCHUNK 64
#define NCHUNK 17            // 16 h-chunks + 1 x-chunk (x last)
#define NBLK 256

// ---------------- persistent device scratch (allocation-free) ----------------
__device__ __half g_Wt[(size_t)NGATE * KTOT];     // fp16 weights, [n'][k] K-major
__device__ float  g_b2[NGATE];                    // bias reordered to n'
__device__ __half g_in[(size_t)BSZ * TIN * FDIM]; // fp16 inputs
__device__ __half g_hA[(size_t)BSZ * UNITS];
__device__ __half g_hB[(size_t)BSZ * UNITS];
__device__ float  g_hf32[(size_t)BSZ * UNITS];    // fp32 h (decode region only)
__device__ float  g_c[(size_t)BSZ * UNITS];
__device__ __half g_xd[(size_t)BSZ * FDIM];       // decode input = fp16(pred)
__device__ unsigned g_bar[2];                     // [0]=count, [1]=generation
__device__ int    g_xflag;                        // 256 * (#denses completed)

__device__ __forceinline__ uint32_t smem_u32(const void* p) {
    uint32_t a;
    asm("{ .reg .u64 t; cvta.to.shared.u64 t, %1; cvt.u32.u64 %0, t; }" : "=r"(a) : "l"(p));
    return a;
}
__device__ __forceinline__ void cp16(uint32_t saddr, const void* g) {
    asm volatile("cp.async.cg.shared.global [%0], [%1], 16;" :: "r"(saddr), "l"(g));
}
__device__ __forceinline__ void cp_commit() {
    asm volatile("cp.async.commit_group;" ::: "memory");
}
template <int N>
__device__ __forceinline__ void cp_wait() {
    asm volatile("cp.async.wait_group %0;" :: "n"(N) : "memory");
}
__device__ __forceinline__ void ldm4(uint32_t* r, uint32_t addr) {
    asm volatile("ldmatrix.sync.aligned.m8n8.x4.shared.b16 {%0,%1,%2,%3}, [%4];"
        : "=r"(r[0]), "=r"(r[1]), "=r"(r[2]), "=r"(r[3]) : "r"(addr));
}
__device__ __forceinline__ void mma16816(float* d, const uint32_t* a, const uint32_t* b) {
    asm volatile(
        "mma.sync.aligned.m16n8k16.row.col.f32.f16.f16.f32 "
        "{%0,%1,%2,%3}, {%4,%5,%6,%7}, {%8,%9}, {%0,%1,%2,%3};"
        : "+f"(d[0]), "+f"(d[1]), "+f"(d[2]), "+f"(d[3])
        : "r"(a[0]), "r"(a[1]), "r"(a[2]), "r"(a[3]), "r"(b[0]), "r"(b[1]));
}
__device__ __forceinline__ float sigm(float x) {
    return __fdividef(1.0f, 1.0f + __expf(-x));
}
__device__ __forceinline__ float ftanh(float x) {
    return __fdividef(2.0f, 1.0f + __expf(-2.0f * x)) - 1.0f;
}

#define SWZ(o) ((o) ^ (((o) >> 3) & 0x70))

// ---------------- SMEM layout ----------------
// [0,512): bias. Stages (3 x 24KB): A(8K)+B(16K) each, chunk c -> stage c%3.
// z/dense scratch: separate 33792 B region after the stages.
#define A_TILE_B 8192
#define STAGE_B 24576
#define SM_STG 512
#define SM_ZS (SM_STG + 3 * STAGE_B)            // 74240
#define SM_TOTAL (SM_ZS + 33792)                // 108032 (2 CTAs/SM: 216KB < 228KB)

__device__ __forceinline__ void grid_barrier(unsigned target) {
    __threadfence();
    __syncthreads();
    if (threadIdx.x == 0) {
        if (atomicAdd(&g_bar[0], 1u) == NBLK - 1u) {
            atomicExch(&g_bar[0], 0u);
            __threadfence();
            atomicExch(&g_bar[1], target);
        } else {
            while (((volatile unsigned*)g_bar)[1] < target) __nanosleep(32);
            __threadfence();
        }
    }
    __syncthreads();
}

__global__ __launch_bounds__(256, 2)
void lstm_persist(const float* __restrict__ Wd,
                  const float* __restrict__ bd,
                  float* __restrict__ out)
{
    extern __shared__ char smem[];
    const uint32_t sbase = smem_u32(smem);
    const int tid = threadIdx.x, wid = tid >> 5, lane = tid & 31;
    const int warp_m = wid >> 2;            // 0..1 -> rows warp_m*32
    const int warp_n = wid & 3;             // 0..3 -> cols warp_n*32
    const int m0 = blockIdx.x * 64;         // batch tile (M=64)
    const int n0 = blockIdx.y * 128;        // gate-interleaved col base (N=128)
    const int u0 = blockIdx.y * 32;
    const int flat = blockIdx.y * gridDim.x + blockIdx.x;

    if (tid < 128) ((float*)smem)[tid] = g_b2[n0 + tid];

    const __half* __restrict__ Bw = g_Wt + (size_t)n0 * KTOT;

    const int a_r  = warp_m * 32 + (lane & 15);
    const int a_cs = (lane >> 4) * 16;
    const int b_r  = warp_n * 32 + (lane & 7) + ((lane >> 4) << 3);
    const int b_cs = ((lane >> 3) & 1) * 16;

    unsigned lgen = 0;
    float acc[2][4][4];

    auto issueW = [&](int c, int st) {
        const uint32_t sb = sbase + SM_STG + st * STAGE_B + A_TILE_B;
        #pragma unroll
        for (int i = 0; i < 4; ++i) {
            const int idx = i * 256 + tid;
            const int row = idx >> 3, ch = idx & 7;
            cp16(sb + SWZ(row * 128 + ch * 16),
                 Bw + (size_t)row * KTOT + c * KCHUNK + ch * 8);
        }
    };
    auto issueA = [&](const __half* hptr, const __half* xptr, int xs, int c, int st) {
        const __half* ap;
        int lda;
        if (c < 16) { ap = hptr + (size_t)m0 * UNITS + c * KCHUNK; lda = UNITS; }
        else        { ap = xptr + (size_t)m0 * xs;                 lda = xs; }
        const uint32_t sb = sbase + SM_STG + st * STAGE_B;
        #pragma unroll
        for (int i = 0; i < 2; ++i) {
            const int idx = i * 256 + tid;
            const int row = idx >> 3, ch = idx & 7;
            cp16(sb + SWZ(row * 128 + ch * 16), ap + (size_t)row * lda + ch * 8);
        }
    };
    auto compute = [&](int st) {
        const uint32_t sb = sbase + SM_STG + st * STAGE_B;
        #pragma unroll
        for (int k16 = 0; k16 < 4; ++k16) {
            const int kb = k16 * 32;
            uint32_t ah[2][4], bh[2][4];
            #pragma unroll
            for (int mf = 0; mf < 2; ++mf)
                ldm4(ah[mf], sb + SWZ((a_r + mf * 16) * 128 + kb + a_cs));
            #pragma unroll
            for (int p = 0; p < 2; ++p)
                ldm4(bh[p], sb + A_TILE_B + SWZ((b_r + p * 16) * 128 + kb + b_cs));
            #pragma unroll
            for (int mf = 0; mf < 2; ++mf)
                #pragma unroll
                for (int nf = 0; nf < 4; ++nf)
                    mma16816(acc[mf][nf], ah[mf], &bh[nf >> 1][(nf & 1) * 2]);
        }
    };

    auto epilogue = [&](int t, __half* ho) {
        float* zs = (float*)(smem + SM_ZS);
        __syncthreads();
        {
            const int gr = lane >> 2, gcn = (lane & 3) * 2;
            #pragma unroll
            for (int mf = 0; mf < 2; ++mf)
                #pragma unroll
                for (int nf = 0; nf < 4; ++nf) {
                    const int row = warp_m * 32 + mf * 16 + gr;
                    const int col = warp_n * 32 + nf * 8 + gcn;
                    *(float2*)&zs[row * 132 + col]       = make_float2(acc[mf][nf][0], acc[mf][nf][1]);
                    *(float2*)&zs[(row + 8) * 132 + col] = make_float2(acc[mf][nf][2], acc[mf][nf][3]);
                }
        }
        __syncthreads();
        {
            const int m  = tid >> 2;
            const int ub = (tid & 3) * 8;
            const float4* zrow  = (const float4*)&zs[m * 132];
            const float4* bias4 = (const float4*)smem;
            const size_t idx0 = (size_t)(m0 + m) * UNITS + u0 + ub;
            __align__(16) float cf[8], hfv[8];
            __align__(8) __half hh[8];
            if (t == 0) {
                #pragma unroll
                for (int j = 0; j < 8; ++j) cf[j] = 0.f;
            } else {
                *(float4*)&cf[0] = *(const float4*)(g_c + idx0);
                *(float4*)&cf[4] = *(const float4*)(g_c + idx0 + 4);
            }
            #pragma unroll
            for (int j = 0; j < 8; ++j) {
                const int ul = ub + j;
                const float4 z4 = zrow[ul];
                const float4 bb = bias4[ul];
                const float zi = z4.x + bb.x;
                const float zf = z4.y + bb.y;
                const float zg = z4.z + bb.z;
                const float zo = z4.w + bb.w;
                const float cn = sigm(zf) * cf[j] + sigm(zi) * ftanh(zg);
                cf[j] = cn;
                const float h = sigm(zo) * ftanh(cn);
                hfv[j] = h;
                hh[j] = __float2half(h);
            }
            *(float4*)(g_c + idx0)     = *(const float4*)&cf[0];
            *(float4*)(g_c + idx0 + 4) = *(const float4*)&cf[4];
            *(uint4*)(ho + idx0) = *(const uint4*)&hh[0];
            if (t >= TIN - 1) {
                *(float4*)(g_hf32 + idx0)     = *(const float4*)&hfv[0];
                *(float4*)(g_hf32 + idx0 + 4) = *(const float4*)&hfv[4];
            }
        }
    };

    // dense head: this CTA handles 8 batches x 16 f; h tile staged in SMEM
    auto dense = [&](int ds) {
        const int bg = flat >> 2;      // 0..63
        const int fg = flat & 3;       // 0..3
        float* hs = (float*)(smem + SM_ZS);   // 8 x 1024 floats
        const float4* src = (const float4*)(g_hf32 + (size_t)(bg * 8) * UNITS);
        float4* dst4 = (float4*)hs;
        #pragma unroll
        for (int i = 0; i < 8; ++i)
            dst4[i * 256 + tid] = __ldcg(src + i * 256 + tid);
        __syncthreads();
        if (tid < 128) {
            const int bl = tid >> 4;               // 0..7
            const int f  = fg * 16 + (tid & 15);
            const float* hrow = hs + bl * 1024;
            float a0 = 0.f;
            #pragma unroll 8
            for (int k = 0; k < UNITS; ++k)
                a0 = fmaf(hrow[k], Wd[k * FDIM + f], a0);
            const float p = a0 + bd[f];
            const int b = bg * 8 + bl;
            out[(size_t)b * (OUT_STEPS * FDIM) + (size_t)ds * FDIM + f] = p;
            g_xd[(size_t)b * FDIM + f] = __float2half(p);
        }
        __syncthreads();
        __threadfence();
        if (tid == 0) atomicAdd(&g_xflag, 1);
    };

    // ---------------- step 0: only the x chunk (h=0, c=0) ----------------
    {
        issueA(nullptr, g_in, TIN * FDIM, 16, 1);
        issueW(16, 1);
        cp_commit();
        #pragma unroll
        for (int i = 0; i < 2; ++i)
            #pragma unroll
            for (int j = 0; j < 4; ++j)
                #pragma unroll
                for (int r = 0; r < 4; ++r) acc[i][j][r] = 0.f;
        cp_wait<0>();
        __syncthreads();
        compute(1);
        epilogue(0, g_hB);                 // h(1) -> g_hB
        issueW(0, 0); issueW(1, 1); cp_commit();   // Gpre for step 1
        grid_barrier(++lgen);
        issueA(g_hB, nullptr, 0, 0, 0); cp_commit();   // GA0
        issueA(g_hB, nullptr, 0, 1, 1); cp_commit();   // GA1
    }

    // ---------------- steps 1..158 ----------------
    #pragma unroll 1
    for (int t = 1; t < NSTEPS; ++t) {
        const __half* hi = (t & 1) ? g_hB : g_hA;
        __half* ho       = (t & 1) ? g_hA : g_hB;
        const __half* xp;
        int xstride;
        if (t < TIN) { xp = g_in + (size_t)t * FDIM; xstride = TIN * FDIM; }
        else         { xp = g_xd; xstride = FDIM; }

        #pragma unroll
        for (int i = 0; i < 2; ++i)
            #pragma unroll
            for (int j = 0; j < 4; ++j)
                #pragma unroll
                for (int r = 0; r < 4; ++r) acc[i][j][r] = 0.f;

        #pragma unroll 1
        for (int c = 0; c < NCHUNK; ++c) {
            if (c == 16) cp_wait<0>(); else cp_wait<1>();
            __syncthreads();
            if (c + 2 <= 16) {
                const int cn = c + 2;
                if (cn == 16 && t >= TIN) {      // x depends on dense of this step's input
                    const int tgt = NBLK * (t - TIN + 1);
                    volatile const int* vp = (volatile const int*)&g_xflag;
                    while (*vp < tgt) __nanosleep(32);
                    __threadfence();
                }
                issueA(hi, xp, xstride, cn, cn % 3);
                issueW(cn, cn % 3);
                cp_commit();
            }
            compute(c % 3);
        }

        epilogue(t, ho);

        if (t + 1 < NSTEPS) { issueW(0, 0); issueW(1, 1); cp_commit(); }  // Gpre(t+1)
        grid_barrier(++lgen);
        if (t + 1 < NSTEPS) {
            // issue next step's first two h chunks before doing dense work
            const __half* hn = ho;
            issueA(hn, nullptr, 0, 0, 0); cp_commit();   // GA0
            issueA(hn, nullptr, 0, 1, 1); cp_commit();   // GA1
        }
        if (t >= TIN - 1) dense(t - (TIN - 1));
    }
}

// ---------------- preprocessing: coalesced tiled transpose to fp16 ----------------
__global__ __launch_bounds__(256)
void prep_weights(const float* __restrict__ Wk, const float* __restrict__ Wr,
                  const float* __restrict__ b) {
    __shared__ float tile[64][65];            // [n'_loc][k_loc]
    const int k0 = blockIdx.x * 64;
    const int u0 = blockIdx.y * 16;
    const int r  = threadIdx.x >> 2;
    const int cq = threadIdx.x & 3;
    const int k  = k0 + r;
    #pragma unroll
    for (int g = 0; g < 4; ++g) {
        const int col = g * UNITS + u0 + cq * 4;
        float4 v;
        if (k < UNITS) v = *(const float4*)(Wr + (size_t)k * NGATE + col);
        else           v = *(const float4*)(Wk + (size_t)(k - UNITS) * NGATE + col);
        tile[(cq * 4 + 0) * 4 + g][r] = v.x;
        tile[(cq * 4 + 1) * 4 + g][r] = v.y;
        tile[(cq * 4 + 2) * 4 + g][r] = v.z;
        tile[(cq * 4 + 3) * 4 + g][r] = v.w;
    }
    if (blockIdx.x == 0 && blockIdx.y == 0)
        for (int i = threadIdx.x; i < NGATE; i += 256)
            g_b2[i] = b[(i & 3) * UNITS + (i >> 2)];
    __syncthreads();
    const int nl = threadIdx.x >> 2;
    const int kk = (threadIdx.x & 3) * 16;
    const size_t ng = (size_t)(blockIdx.y * 64 + nl);
    __align__(16) __half hb[16];
    #pragma unroll
    for (int j = 0; j < 16; ++j)
        hb[j] = __float2half(tile[nl][kk + j]);
    *(uint4*)(g_Wt + ng * KTOT + k0 + kk)     = *(const uint4*)&hb[0];
    *(uint4*)(g_Wt + ng * KTOT + k0 + kk + 8) = *(const uint4*)&hb[8];
}

__global__ void prep_inputs(const float* __restrict__ inp) {
    const size_t idx = (size_t)blockIdx.x * blockDim.x + threadIdx.x;
    if (idx < (size_t)BSZ * TIN * FDIM)
        g_in[idx] = __float2half(inp[idx]);
}

// ---------------- launch ----------------
extern "C" void kernel_launch(void* const* d_in, const int* in_sizes, int n_in,
                              void* d_out, int out_size)
{
    const float* inputs = (const float*)d_in[0];
    const float* Wk     = (const float*)d_in[1];
    const float* Wr     = (const float*)d_in[2];
    const float* bias   = (const float*)d_in[3];
    const float* Wd     = (const float*)d_in[4];
    const float* bd     = (const float*)d_in[5];
    float* out = (float*)d_out;

    static bool attr_done = false;
    if (!attr_done) {
        cudaFuncSetAttribute(lstm_persist, cudaFuncAttributeMaxDynamicSharedMemorySize, SM_TOTAL);
        attr_done = true;
    }

    void* bar_addr; void* xflag_addr;
    cudaGetSymbolAddress(&bar_addr, g_bar);
    cudaGetSymbolAddress(&xflag_addr, g_xflag);
    cudaMemsetAsync(bar_addr, 0, 2 * sizeof(unsigned));
    cudaMemsetAsync(xflag_addr, 0, sizeof(int));

    prep_weights<<<dim3(17, 64), 256>>>(Wk, Wr, bias);
    {
        const size_t ni = (size_t)BSZ * TIN * FDIM;
        prep_inputs<<<(unsigned)((ni + 255) / 256), 256>>>(inputs);
    }

    lstm_persist<<<dim3(BSZ / 64, NGATE / 128), 256, SM_TOTAL>>>(Wd, bd, out);
}

// round 10
// speedup vs baseline: 1.0030x; 1.0030x over previous
#include <cuda_runtime.h>
#include <cuda_fp16.h>
#include <stdint.h>
#include <math.h>

#define BSZ 512
#define TIN 128
#define FDIM 64
#define UNITS 1024
#define OUT_STEPS 32
#define NSTEPS 159           // TIN + OUT_STEPS - 1 LSTM steps
#define NGATE 4096           // 4*UNITS, gate-interleaved: n' = u*4 + g
#define KTOT 1088            // 1024 (h) + 64 (x)
#define KCHUNK 64
#define NCHUNK 17            // 16 h-chunks + 1 x-chunk
#define NBLK 256

// ---------------- persistent device scratch (allocation-free) ----------------
__device__ __half g_Wt[(size_t)NGATE * KTOT];     // fp16 weights, [n'][k] K-major
__device__ float  g_b2[NGATE];                    // bias reordered to n'
__device__ __half g_in[(size_t)BSZ * TIN * FDIM]; // fp16 inputs
__device__ __half g_hA[(size_t)BSZ * UNITS];
__device__ __half g_hB[(size_t)BSZ * UNITS];
__device__ float  g_hf32[(size_t)BSZ * UNITS];    // fp32 h (decode region only)
__device__ __half g_xd[(size_t)BSZ * FDIM];       // decode input = fp16(pred)
__device__ unsigned g_bar1[8 * 32];               // level-1 counters (1 per batch lane, 128B apart)
__device__ unsigned g_bar2[32];                   // [0]=root count, [16]=generation

__device__ __forceinline__ uint32_t smem_u32(const void* p) {
    uint32_t a;
    asm("{ .reg .u64 t; cvta.to.shared.u64 t, %1; cvt.u32.u64 %0, t; }" : "=r"(a) : "l"(p));
    return a;
}
__device__ __forceinline__ void cp16(uint32_t saddr, const void* g) {
    asm volatile("cp.async.cg.shared.global [%0], [%1], 16;" :: "r"(saddr), "l"(g));
}
__device__ __forceinline__ void cp_commit() {
    asm volatile("cp.async.commit_group;" ::: "memory");
}
template <int N>
__device__ __forceinline__ void cp_wait() {
    asm volatile("cp.async.wait_group %0;" :: "n"(N) : "memory");
}
__device__ __forceinline__ void ldm4(uint32_t* r, uint32_t addr) {
    asm volatile("ldmatrix.sync.aligned.m8n8.x4.shared.b16 {%0,%1,%2,%3}, [%4];"
        : "=r"(r[0]), "=r"(r[1]), "=r"(r[2]), "=r"(r[3]) : "r"(addr));
}
// mma.sync m16n8k16 row.col fp16 -> f32 (baseline PTX)
__device__ __forceinline__ void mma16816(float* d, const uint32_t* a, const uint32_t* b) {
    asm volatile(
        "mma.sync.aligned.m16n8k16.row.col.f32.f16.f16.f32 "
        "{%0,%1,%2,%3}, {%4,%5,%6,%7}, {%8,%9}, {%0,%1,%2,%3};"
        : "+f"(d[0]), "+f"(d[1]), "+f"(d[2]), "+f"(d[3])
        : "r"(a[0]), "r"(a[1]), "r"(a[2]), "r"(a[3]), "r"(b[0]), "r"(b[1]));
}
__device__ __forceinline__ float sigm(float x) {
    return __fdividef(1.0f, 1.0f + __expf(-x));
}
__device__ __forceinline__ float ftanh(float x) {
    return __fdividef(2.0f, 1.0f + __expf(-2.0f * x)) - 1.0f;
}

#define SWZ(o) ((o) ^ (((o) >> 3) & 0x70))

// ---------------- SMEM layout ----------------
// [0,512): bias (128 floats).
// Stage (24 KB): A(64x128B)=8K @0, B(128x128B)=16K @8192. Two stages.
// z scratch (64x132 f32 = 33792 B) overlays stage 1 + tail (last chunk c=16 uses stage 0).
#define A_TILE_B 8192
#define B_TILE_B 16384
#define STAGE_B 24576
#define SM_STG 512
#define SM_TOTAL (SM_STG + STAGE_B + 33792)   // 58880

// Two-level barrier: 32 arrivals per batch-lane counter, then 8 on the root.
__device__ __forceinline__ void grid_barrier(int bx, unsigned target) {
    __threadfence();
    __syncthreads();
    if (threadIdx.x == 0) {
        if (atomicAdd(&g_bar1[bx * 32], 1u) == 31u) {
            atomicExch(&g_bar1[bx * 32], 0u);
            if (atomicAdd(&g_bar2[0], 1u) == 7u) {
                atomicExch(&g_bar2[0], 0u);
                __threadfence();
                atomicExch(&g_bar2[16], target);
            }
        }
        while (((volatile unsigned*)g_bar2)[16] < target) __nanosleep(32);
        __threadfence();
    }
    __syncthreads();
}

__global__ __launch_bounds__(256, 2)
void lstm_persist(const float* __restrict__ Wd,
                  const float* __restrict__ bd,
                  float* __restrict__ out)
{
    extern __shared__ char smem[];
    const uint32_t sbase = smem_u32(smem);
    const int tid = threadIdx.x, wid = tid >> 5, lane = tid & 31;
    const int warp_m = wid >> 2;            // 0..1 -> rows warp_m*32
    const int warp_n = wid & 3;             // 0..3 -> cols warp_n*32
    const int bx = blockIdx.x;
    const int m0 = bx * 64;                 // batch tile (M=64)
    const int n0 = blockIdx.y * 128;        // gate-interleaved column base (N=128)
    const int u0 = blockIdx.y * 32;
    const int flat = blockIdx.y * gridDim.x + bx;

    if (tid < 128) ((float*)smem)[tid] = g_b2[n0 + tid];

    const __half* __restrict__ Bw = g_Wt + (size_t)n0 * KTOT;

    const int a_r  = warp_m * 32 + (lane & 15);
    const int a_cs = (lane >> 4) * 16;
    const int b_r  = warp_n * 32 + (lane & 7) + ((lane >> 4) << 3);
    const int b_cs = ((lane >> 3) & 1) * 16;

    unsigned lgen = 0;

    // persistent cell state: this (CTA, thread) owns the same 8 units forever
    float cf[8];
    #pragma unroll
    for (int j = 0; j < 8; ++j) cf[j] = 0.f;

    // W loader (weights are step-invariant)
    auto issueW = [&](int c, int st) {
        const uint32_t sb = sbase + SM_STG + st * STAGE_B + A_TILE_B;
        #pragma unroll
        for (int i = 0; i < 4; ++i) {
            const int idx = i * 256 + tid;
            const int row = idx >> 3, ch = idx & 7;
            const uint32_t so = SWZ(row * 128 + ch * 16);
            cp16(sb + so, Bw + (size_t)row * KTOT + c * KCHUNK + ch * 8);
        }
    };

    #pragma unroll 1
    for (int t = 0; t < NSTEPS; ++t) {
        const __half* hi = (t & 1) ? g_hB : g_hA;
        __half* ho       = (t & 1) ? g_hA : g_hB;
        const __half* xp;
        int xstride;
        if (t < TIN) { xp = g_in + (size_t)t * FDIM; xstride = TIN * FDIM; }
        else         { xp = g_xd; xstride = FDIM; }

        auto issueA = [&](int c, int st) {
            const __half* ap;
            int lda;
            if (c < 16) { ap = hi + (size_t)m0 * UNITS + c * KCHUNK; lda = UNITS; }
            else        { ap = xp + (size_t)m0 * xstride;            lda = xstride; }
            const uint32_t sb = sbase + SM_STG + st * STAGE_B;
            #pragma unroll
            for (int i = 0; i < 2; ++i) {
                const int idx = i * 256 + tid;
                const int row = idx >> 3, ch = idx & 7;
                const uint32_t so = SWZ(row * 128 + ch * 16);
                cp16(sb + so, ap + (size_t)row * lda + ch * 8);
            }
        };

        int c0;
        if (t == 0) { c0 = 16; issueA(16, 0); issueW(16, 0); cp_commit(); }
        else        { c0 = 0;  issueA(0, 0);  cp_commit(); }   // W0 pre-issued last step

        float acc[2][4][4];
        #pragma unroll
        for (int i = 0; i < 2; ++i)
            #pragma unroll
            for (int j = 0; j < 4; ++j)
                #pragma unroll
                for (int r = 0; r < 4; ++r) acc[i][j][r] = 0.f;

        #pragma unroll 1
        for (int c = c0; c < NCHUNK; ++c) {
            const int st = c & 1;
            cp_wait<0>();
            __syncthreads();
            if (c + 1 < NCHUNK) { issueA(c + 1, st ^ 1); issueW(c + 1, st ^ 1); cp_commit(); }

            const uint32_t sb = sbase + SM_STG + st * STAGE_B;
            #pragma unroll
            for (int k16 = 0; k16 < 4; ++k16) {
                const int kb = k16 * 32;
                uint32_t ah[2][4], bh[2][4];
                #pragma unroll
                for (int mf = 0; mf < 2; ++mf) {
                    const uint32_t so = SWZ((a_r + mf * 16) * 128 + kb + a_cs);
                    ldm4(ah[mf], sb + so);
                }
                #pragma unroll
                for (int p = 0; p < 2; ++p) {
                    const uint32_t so = SWZ((b_r + p * 16) * 128 + kb + b_cs);
                    ldm4(bh[p], sb + A_TILE_B + so);
                }
                #pragma unroll
                for (int mf = 0; mf < 2; ++mf)
                    #pragma unroll
                    for (int nf = 0; nf < 4; ++nf)
                        mma16816(acc[mf][nf], ah[mf], &bh[nf >> 1][(nf & 1) * 2]);
            }
        }

        // ---- epilogue: z scratch overlays stage 1 (last chunk c=16 computed from stage 0) ----
        float* zs = (float*)(smem + SM_STG + STAGE_B);
        __syncthreads();
        {
            const int gr = lane >> 2, gcn = (lane & 3) * 2;
            #pragma unroll
            for (int mf = 0; mf < 2; ++mf)
                #pragma unroll
                for (int nf = 0; nf < 4; ++nf) {
                    const int row = warp_m * 32 + mf * 16 + gr;
                    const int col = warp_n * 32 + nf * 8 + gcn;
                    *(float2*)&zs[row * 132 + col]       = make_float2(acc[mf][nf][0], acc[mf][nf][1]);
                    *(float2*)&zs[(row + 8) * 132 + col] = make_float2(acc[mf][nf][2], acc[mf][nf][3]);
                }
        }
        __syncthreads();
        {
            const int m  = tid >> 2;
            const int ub = (tid & 3) * 8;
            const float4* zrow  = (const float4*)&zs[m * 132];
            const float4* bias4 = (const float4*)smem;
            const size_t idx0 = (size_t)(m0 + m) * UNITS + u0 + ub;
            __align__(16) float hfv[8];
            __align__(8) __half hh[8];
            #pragma unroll
            for (int j = 0; j < 8; ++j) {
                const int ul = ub + j;
                const float4 z4 = zrow[ul];
                const float4 bb = bias4[ul];
                const float zi = z4.x + bb.x;
                const float zf = z4.y + bb.y;
                const float zg = z4.z + bb.z;
                const float zo = z4.w + bb.w;
                const float cn = sigm(zf) * cf[j] + sigm(zi) * ftanh(zg);
                cf[j] = cn;
                const float h = sigm(zo) * ftanh(cn);
                hfv[j] = h;
                hh[j] = __float2half(h);
            }
            *(uint4*)(ho + idx0) = *(const uint4*)&hh[0];
            if (t >= TIN - 1) {   // fp32 h needed only by the dense head
                *(float4*)(g_hf32 + idx0)     = *(const float4*)&hfv[0];
                *(float4*)(g_hf32 + idx0 + 4) = *(const float4*)&hfv[4];
            }
        }

        if (t + 1 < NSTEPS) { issueW(0, 0); cp_commit(); }   // prefetch next step's W0 across the barrier
        grid_barrier(bx, ++lgen);

        if (t >= TIN - 1) {
            const int ds = t - (TIN - 1);
            if (flat < 64) {
                const int bg = flat >> 3;
                const int fg = flat & 7;
                const int bl_ = tid >> 2;
                const int f0 = fg * 8 + (tid & 3);
                const int b  = bg * 64 + bl_;
                const float4* hp = (const float4*)(g_hf32 + (size_t)b * UNITS);
                float a0 = 0.f, a1 = 0.f;
                #pragma unroll 4
                for (int kq = 0; kq < UNITS / 4; ++kq) {
                    const float4 hv = __ldcg(hp + kq);
                    const float* w = Wd + (size_t)kq * 4 * FDIM;
                    a0 = fmaf(hv.x, w[f0], a0);            a1 = fmaf(hv.x, w[f0 + 4], a1);
                    a0 = fmaf(hv.y, w[64 + f0], a0);       a1 = fmaf(hv.y, w[64 + f0 + 4], a1);
                    a0 = fmaf(hv.z, w[128 + f0], a0);      a1 = fmaf(hv.z, w[128 + f0 + 4], a1);
                    a0 = fmaf(hv.w, w[192 + f0], a0);      a1 = fmaf(hv.w, w[192 + f0 + 4], a1);
                }
                const float p0 = a0 + bd[f0];
                const float p1 = a1 + bd[f0 + 4];
                out[(size_t)b * (OUT_STEPS * FDIM) + (size_t)ds * FDIM + f0]     = p0;
                out[(size_t)b * (OUT_STEPS * FDIM) + (size_t)ds * FDIM + f0 + 4] = p1;
                g_xd[(size_t)b * FDIM + f0]     = __float2half(p0);
                g_xd[(size_t)b * FDIM + f0 + 4] = __float2half(p1);
            }
            if (t + 1 < NSTEPS) grid_barrier(bx, ++lgen);
        }
    }
}

// ---------------- preprocessing: coalesced tiled transpose to fp16 ----------------
__global__ __launch_bounds__(256)
void prep_weights(const float* __restrict__ Wk, const float* __restrict__ Wr,
                  const float* __restrict__ b) {
    __shared__ float tile[64][65];            // [n'_loc][k_loc]
    const int k0 = blockIdx.x * 64;
    const int u0 = blockIdx.y * 16;
    const int r  = threadIdx.x >> 2;
    const int cq = threadIdx.x & 3;
    const int k  = k0 + r;
    #pragma unroll
    for (int g = 0; g < 4; ++g) {
        const int col = g * UNITS + u0 + cq * 4;
        float4 v;
        if (k < UNITS) v = *(const float4*)(Wr + (size_t)k * NGATE + col);
        else           v = *(const float4*)(Wk + (size_t)(k - UNITS) * NGATE + col);
        tile[(cq * 4 + 0) * 4 + g][r] = v.x;
        tile[(cq * 4 + 1) * 4 + g][r] = v.y;
        tile[(cq * 4 + 2) * 4 + g][r] = v.z;
        tile[(cq * 4 + 3) * 4 + g][r] = v.w;
    }
    if (blockIdx.x == 0 && blockIdx.y == 0)
        for (int i = threadIdx.x; i < NGATE; i += 256)
            g_b2[i] = b[(i & 3) * UNITS + (i >> 2)];
    __syncthreads();
    const int nl = threadIdx.x >> 2;
    const int kk = (threadIdx.x & 3) * 16;
    const size_t ng = (size_t)(blockIdx.y * 64 + nl);
    __align__(16) __half hb[16];
    #pragma unroll
    for (int j = 0; j < 16; ++j)
        hb[j] = __float2half(tile[nl][kk + j]);
    *(uint4*)(g_Wt + ng * KTOT + k0 + kk)     = *(const uint4*)&hb[0];
    *(uint4*)(g_Wt + ng * KTOT + k0 + kk + 8) = *(const uint4*)&hb[8];
}

__global__ void prep_inputs(const float* __restrict__ inp) {
    const size_t idx = (size_t)blockIdx.x * blockDim.x + threadIdx.x;
    if (idx < (size_t)BSZ * TIN * FDIM)
        g_in[idx] = __float2half(inp[idx]);
}

// ---------------- launch ----------------
extern "C" void kernel_launch(void* const* d_in, const int* in_sizes, int n_in,
                              void* d_out, int out_size)
{
    const float* inputs = (const float*)d_in[0];
    const float* Wk     = (const float*)d_in[1];
    const float* Wr     = (const float*)d_in[2];
    const float* bias   = (const float*)d_in[3];
    const float* Wd     = (const float*)d_in[4];
    const float* bd     = (const float*)d_in[5];
    float* out = (float*)d_out;

    static bool attr_done = false;
    if (!attr_done) {
        cudaFuncSetAttribute(lstm_persist, cudaFuncAttributeMaxDynamicSharedMemorySize, SM_TOTAL);
        attr_done = true;
    }

    void* bar1_addr; void* bar2_addr;
    cudaGetSymbolAddress(&bar1_addr, g_bar1);
    cudaGetSymbolAddress(&bar2_addr, g_bar2);
    cudaMemsetAsync(bar1_addr, 0, 8 * 32 * sizeof(unsigned));
    cudaMemsetAsync(bar2_addr, 0, 32 * sizeof(unsigned));

    prep_weights<<<dim3(17, 64), 256>>>(Wk, Wr, bias);
    {
        const size_t ni = (size_t)BSZ * TIN * FDIM;
        prep_inputs<<<(unsigned)((ni + 255) / 256), 256>>>(inputs);
    }

    lstm_persist<<<dim3(BSZ / 64, NGATE / 128), 256, SM_TOTAL>>>(Wd, bd, out);
}

// round 11
// speedup vs baseline: 1.0666x; 1.0634x over previous
#include <cuda_runtime.h>
#include <cuda_fp16.h>
#include <stdint.h>
#include <math.h>

#define BSZ 512
#define TIN 128
#define FDIM 64
#define UNITS 1024
#define OUT_STEPS 32
#define NSTEPS 159           // TIN + OUT_STEPS - 1 LSTM steps
#define NGATE 4096           // 4*UNITS, gate-interleaved: n' = u*4 + g
#define KTOT 1088            // 1024 (h) + 64 (x)
#define NCHUNK 9             // 8 h-chunks (K=128 each) + 1 x half-chunk (K=64)
#define NBLK 256

// ---------------- persistent device scratch (allocation-free) ----------------
__device__ __half g_Wt[(size_t)NGATE * KTOT];     // fp16 weights, [n'][k] K-major
__device__ float  g_b2[NGATE];                    // bias reordered to n'
__device__ __half g_in[(size_t)BSZ * TIN * FDIM]; // fp16 inputs
__device__ __half g_hA[(size_t)BSZ * UNITS];
__device__ __half g_hB[(size_t)BSZ * UNITS];
__device__ float  g_hf32[(size_t)BSZ * UNITS];    // fp32 h (decode region only)
__device__ __half g_xd[(size_t)BSZ * FDIM];       // decode input = fp16(pred)
__device__ unsigned g_bar1[8 * 32];               // level-1 counters (1/batch lane, 128B apart)
__device__ unsigned g_bar2[32];                   // [0]=root count, [16]=generation

__device__ __forceinline__ uint32_t smem_u32(const void* p) {
    uint32_t a;
    asm("{ .reg .u64 t; cvta.to.shared.u64 t, %1; cvt.u32.u64 %0, t; }" : "=r"(a) : "l"(p));
    return a;
}
__device__ __forceinline__ void cp16(uint32_t saddr, const void* g) {
    asm volatile("cp.async.cg.shared.global [%0], [%1], 16;" :: "r"(saddr), "l"(g));
}
__device__ __forceinline__ void cp_commit() {
    asm volatile("cp.async.commit_group;" ::: "memory");
}
template <int N>
__device__ __forceinline__ void cp_wait() {
    asm volatile("cp.async.wait_group %0;" :: "n"(N) : "memory");
}
__device__ __forceinline__ void ldm4(uint32_t* r, uint32_t addr) {
    asm volatile("ldmatrix.sync.aligned.m8n8.x4.shared.b16 {%0,%1,%2,%3}, [%4];"
        : "=r"(r[0]), "=r"(r[1]), "=r"(r[2]), "=r"(r[3]) : "r"(addr));
}
// mma.sync m16n8k16 row.col fp16 -> f32 (baseline PTX)
__device__ __forceinline__ void mma16816(float* d, const uint32_t* a, const uint32_t* b) {
    asm volatile(
        "mma.sync.aligned.m16n8k16.row.col.f32.f16.f16.f32 "
        "{%0,%1,%2,%3}, {%4,%5,%6,%7}, {%8,%9}, {%0,%1,%2,%3};"
        : "+f"(d[0]), "+f"(d[1]), "+f"(d[2]), "+f"(d[3])
        : "r"(a[0]), "r"(a[1]), "r"(a[2]), "r"(a[3]), "r"(b[0]), "r"(b[1]));
}
__device__ __forceinline__ float sigm(float x) {
    return __fdividef(1.0f, 1.0f + __expf(-x));
}
__device__ __forceinline__ float ftanh(float x) {
    return __fdividef(2.0f, 1.0f + __expf(-2.0f * x)) - 1.0f;
}

#define SWZ(o) ((o) ^ (((o) >> 3) & 0x70))

// ---------------- SMEM layout ----------------
// [0,512): bias (128 floats).
// Stage (48 KB): A = 2 sub-tiles of 8K (64 rows x 128B) @0, @8192;
//                B = 2 sub-tiles of 16K (128 rows x 128B) @16384, @32768.
// Two stages. Chunk c -> stage c&1 (last chunk c=8 -> stage 0).
// z scratch (64x132 f32 = 33792 B) overlays stage 1.
#define A_SUB_B 8192
#define A_TILE_B 16384
#define B_SUB_B 16384
#define STAGE_B 49152
#define SM_STG 512
#define SM_ZS (SM_STG + STAGE_B)
#define SM_TOTAL (SM_STG + 2 * STAGE_B)   // 98816 (2 CTAs/SM: 197KB < 228KB)

// Two-level barrier: 32 arrivals per batch-lane counter, then 8 on the root.
__device__ __forceinline__ void grid_barrier(int bx, unsigned target) {
    __threadfence();
    __syncthreads();
    if (threadIdx.x == 0) {
        if (atomicAdd(&g_bar1[bx * 32], 1u) == 31u) {
            atomicExch(&g_bar1[bx * 32], 0u);
            if (atomicAdd(&g_bar2[0], 1u) == 7u) {
                atomicExch(&g_bar2[0], 0u);
                __threadfence();
                atomicExch(&g_bar2[16], target);
            }
        }
        while (((volatile unsigned*)g_bar2)[16] < target) __nanosleep(32);
        __threadfence();
    }
    __syncthreads();
}

__global__ __launch_bounds__(256, 2)
void lstm_persist(const float* __restrict__ Wd,
                  const float* __restrict__ bd,
                  float* __restrict__ out)
{
    extern __shared__ char smem[];
    const uint32_t sbase = smem_u32(smem);
    const int tid = threadIdx.x, wid = tid >> 5, lane = tid & 31;
    const int warp_m = wid >> 2;            // 0..1 -> rows warp_m*32
    const int warp_n = wid & 3;             // 0..3 -> cols warp_n*32
    const int bx = blockIdx.x;
    const int m0 = bx * 64;                 // batch tile (M=64)
    const int n0 = blockIdx.y * 128;        // gate-interleaved column base (N=128)
    const int u0 = blockIdx.y * 32;
    const int flat = blockIdx.y * gridDim.x + bx;

    if (tid < 128) ((float*)smem)[tid] = g_b2[n0 + tid];

    const __half* __restrict__ Bw = g_Wt + (size_t)n0 * KTOT;

    const int a_r  = warp_m * 32 + (lane & 15);
    const int a_cs = (lane >> 4) * 16;
    const int b_r  = warp_n * 32 + (lane & 7) + ((lane >> 4) << 3);
    const int b_cs = ((lane >> 3) & 1) * 16;

    unsigned lgen = 0;

    // persistent cell state: this (CTA, thread) owns the same 8 units forever
    float cf[8];
    #pragma unroll
    for (int j = 0; j < 8; ++j) cf[j] = 0.f;

    float acc[2][4][4];

    // W loader: chunk c covers k = c*128 + sub*64 (c=8: one sub only, k=1024..1087)
    auto issueW = [&](int c, int st) {
        const int nsub = (c == 8) ? 1 : 2;
        for (int s = 0; s < nsub; ++s) {
            const uint32_t sb = sbase + SM_STG + st * STAGE_B + A_TILE_B + s * B_SUB_B;
            const __half* wp = Bw + (size_t)(c * 128 + s * 64);
            #pragma unroll
            for (int i = 0; i < 4; ++i) {
                const int idx = i * 256 + tid;
                const int row = idx >> 3, ch = idx & 7;
                cp16(sb + SWZ(row * 128 + ch * 16), wp + (size_t)row * KTOT + ch * 8);
            }
        }
    };

    // one k16 iteration of the warp-tile MMA
    auto computeK = [&](uint32_t stg, int k16) {
        const int sub = k16 >> 2;
        const int kb = (k16 & 3) * 32;
        uint32_t ah[2][4], bh[2][4];
        #pragma unroll
        for (int mf = 0; mf < 2; ++mf)
            ldm4(ah[mf], stg + sub * A_SUB_B + SWZ((a_r + mf * 16) * 128 + kb + a_cs));
        #pragma unroll
        for (int p = 0; p < 2; ++p)
            ldm4(bh[p], stg + A_TILE_B + sub * B_SUB_B + SWZ((b_r + p * 16) * 128 + kb + b_cs));
        #pragma unroll
        for (int mf = 0; mf < 2; ++mf)
            #pragma unroll
            for (int nf = 0; nf < 4; ++nf)
                mma16816(acc[mf][nf], ah[mf], &bh[nf >> 1][(nf & 1) * 2]);
    };

    #pragma unroll 1
    for (int t = 0; t < NSTEPS; ++t) {
        const __half* hi = (t & 1) ? g_hB : g_hA;
        __half* ho       = (t & 1) ? g_hA : g_hB;
        const __half* xp;
        int xstride;
        if (t < TIN) { xp = g_in + (size_t)t * FDIM; xstride = TIN * FDIM; }
        else         { xp = g_xd; xstride = FDIM; }

        auto issueA = [&](int c, int st) {
            const int nsub = (c == 8) ? 1 : 2;
            for (int s = 0; s < nsub; ++s) {
                const __half* ap;
                int lda;
                if (c < 8) { ap = hi + (size_t)m0 * UNITS + c * 128 + s * 64; lda = UNITS; }
                else       { ap = xp + (size_t)m0 * xstride;                  lda = xstride; }
                const uint32_t sb = sbase + SM_STG + st * STAGE_B + s * A_SUB_B;
                #pragma unroll
                for (int i = 0; i < 2; ++i) {
                    const int idx = i * 256 + tid;
                    const int row = idx >> 3, ch = idx & 7;
                    cp16(sb + SWZ(row * 128 + ch * 16), ap + (size_t)row * lda + ch * 8);
                }
            }
        };

        int c0;
        if (t == 0) { c0 = 8; issueA(8, 0); issueW(8, 0); cp_commit(); }  // h=0: x chunk only
        else        { c0 = 0; issueA(0, 0); cp_commit(); }                // W0 pre-issued last step

        #pragma unroll
        for (int i = 0; i < 2; ++i)
            #pragma unroll
            for (int j = 0; j < 4; ++j)
                #pragma unroll
                for (int r = 0; r < 4; ++r) acc[i][j][r] = 0.f;

        #pragma unroll 1
        for (int c = c0; c < NCHUNK; ++c) {
            const int st = c & 1;
            cp_wait<0>();
            __syncthreads();
            if (c + 1 < NCHUNK) { issueA(c + 1, st ^ 1); issueW(c + 1, st ^ 1); cp_commit(); }

            const uint32_t stg = sbase + SM_STG + st * STAGE_B;
            if (c == 8) {
                #pragma unroll
                for (int k16 = 0; k16 < 4; ++k16) computeK(stg, k16);
            } else {
                #pragma unroll
                for (int k16 = 0; k16 < 8; ++k16) computeK(stg, k16);
            }
        }

        // ---- epilogue: z scratch overlays stage 1 (last chunk c=8 computed from stage 0) ----
        float* zs = (float*)(smem + SM_ZS);
        __syncthreads();
        {
            const int gr = lane >> 2, gcn = (lane & 3) * 2;
            #pragma unroll
            for (int mf = 0; mf < 2; ++mf)
                #pragma unroll
                for (int nf = 0; nf < 4; ++nf) {
                    const int row = warp_m * 32 + mf * 16 + gr;
                    const int col = warp_n * 32 + nf * 8 + gcn;
                    *(float2*)&zs[row * 132 + col]       = make_float2(acc[mf][nf][0], acc[mf][nf][1]);
                    *(float2*)&zs[(row + 8) * 132 + col] = make_float2(acc[mf][nf][2], acc[mf][nf][3]);
                }
        }
        __syncthreads();
        {
            const int m  = tid >> 2;
            const int ub = (tid & 3) * 8;
            const float4* zrow  = (const float4*)&zs[m * 132];
            const float4* bias4 = (const float4*)smem;
            const size_t idx0 = (size_t)(m0 + m) * UNITS + u0 + ub;
            __align__(16) float hfv[8];
            __align__(8) __half hh[8];
            #pragma unroll
            for (int j = 0; j < 8; ++j) {
                const int ul = ub + j;
                const float4 z4 = zrow[ul];
                const float4 bb = bias4[ul];
                const float zi = z4.x + bb.x;
                const float zf = z4.y + bb.y;
                const float zg = z4.z + bb.z;
                const float zo = z4.w + bb.w;
                const float cn = sigm(zf) * cf[j] + sigm(zi) * ftanh(zg);
                cf[j] = cn;
                const float h = sigm(zo) * ftanh(cn);
                hfv[j] = h;
                hh[j] = __float2half(h);
            }
            *(uint4*)(ho + idx0) = *(const uint4*)&hh[0];
            if (t >= TIN - 1) {   // fp32 h needed only by the dense head
                *(float4*)(g_hf32 + idx0)     = *(const float4*)&hfv[0];
                *(float4*)(g_hf32 + idx0 + 4) = *(const float4*)&hfv[4];
            }
        }

        if (t + 1 < NSTEPS) { issueW(0, 0); cp_commit(); }   // prefetch next step's W0 across the barrier
        grid_barrier(bx, ++lgen);

        if (t >= TIN - 1) {
            const int ds = t - (TIN - 1);
            if (flat < 64) {
                const int bg = flat >> 3;
                const int fg = flat & 7;
                const int bl_ = tid >> 2;
                const int f0 = fg * 8 + (tid & 3);
                const int b  = bg * 64 + bl_;
                const float4* hp = (const float4*)(g_hf32 + (size_t)b * UNITS);
                float a0 = 0.f, a1 = 0.f;
                #pragma unroll 4
                for (int kq = 0; kq < UNITS / 4; ++kq) {
                    const float4 hv = __ldcg(hp + kq);
                    const float* w = Wd + (size_t)kq * 4 * FDIM;
                    a0 = fmaf(hv.x, w[f0], a0);            a1 = fmaf(hv.x, w[f0 + 4], a1);
                    a0 = fmaf(hv.y, w[64 + f0], a0);       a1 = fmaf(hv.y, w[64 + f0 + 4], a1);
                    a0 = fmaf(hv.z, w[128 + f0], a0);      a1 = fmaf(hv.z, w[128 + f0 + 4], a1);
                    a0 = fmaf(hv.w, w[192 + f0], a0);      a1 = fmaf(hv.w, w[192 + f0 + 4], a1);
                }
                const float p0 = a0 + bd[f0];
                const float p1 = a1 + bd[f0 + 4];
                out[(size_t)b * (OUT_STEPS * FDIM) + (size_t)ds * FDIM + f0]     = p0;
                out[(size_t)b * (OUT_STEPS * FDIM) + (size_t)ds * FDIM + f0 + 4] = p1;
                g_xd[(size_t)b * FDIM + f0]     = __float2half(p0);
                g_xd[(size_t)b * FDIM + f0 + 4] = __float2half(p1);
            }
            if (t + 1 < NSTEPS) grid_barrier(bx, ++lgen);
        }
    }
}

// ---------------- preprocessing: coalesced tiled transpose to fp16 ----------------
__global__ __launch_bounds__(256)
void prep_weights(const float* __restrict__ Wk, const float* __restrict__ Wr,
                  const float* __restrict__ b) {
    __shared__ float tile[64][65];            // [n'_loc][k_loc]
    const int k0 = blockIdx.x * 64;
    const int u0 = blockIdx.y * 16;
    const int r  = threadIdx.x >> 2;
    const int cq = threadIdx.x & 3;
    const int k  = k0 + r;
    #pragma unroll
    for (int g = 0; g < 4; ++g) {
        const int col = g * UNITS + u0 + cq * 4;
        float4 v;
        if (k < UNITS) v = *(const float4*)(Wr + (size_t)k * NGATE + col);
        else           v = *(const float4*)(Wk + (size_t)(k - UNITS) * NGATE + col);
        tile[(cq * 4 + 0) * 4 + g][r] = v.x;
        tile[(cq * 4 + 1) * 4 + g][r] = v.y;
        tile[(cq * 4 + 2) * 4 + g][r] = v.z;
        tile[(cq * 4 + 3) * 4 + g][r] = v.w;
    }
    if (blockIdx.x == 0 && blockIdx.y == 0)
        for (int i = threadIdx.x; i < NGATE; i += 256)
            g_b2[i] = b[(i & 3) * UNITS + (i >> 2)];
    __syncthreads();
    const int nl = threadIdx.x >> 2;
    const int kk = (threadIdx.x & 3) * 16;
    const size_t ng = (size_t)(blockIdx.y * 64 + nl);
    __align__(16) __half hb[16];
    #pragma unroll
    for (int j = 0; j < 16; ++j)
        hb[j] = __float2half(tile[nl][kk + j]);
    *(uint4*)(g_Wt + ng * KTOT + k0 + kk)     = *(const uint4*)&hb[0];
    *(uint4*)(g_Wt + ng * KTOT + k0 + kk + 8) = *(const uint4*)&hb[8];
}

__global__ void prep_inputs(const float* __restrict__ inp) {
    const size_t idx = (size_t)blockIdx.x * blockDim.x + threadIdx.x;
    if (idx < (size_t)BSZ * TIN * FDIM)
        g_in[idx] = __float2half(inp[idx]);
}

// ---------------- launch ----------------
extern "C" void kernel_launch(void* const* d_in, const int* in_sizes, int n_in,
                              void* d_out, int out_size)
{
    const float* inputs = (const float*)d_in[0];
    const float* Wk     = (const float*)d_in[1];
    const float* Wr     = (const float*)d_in[2];
    const float* bias   = (const float*)d_in[3];
    const float* Wd     = (const float*)d_in[4];
    const float* bd     = (const float*)d_in[5];
    float* out = (float*)d_out;

    static bool attr_done = false;
    if (!attr_done) {
        cudaFuncSetAttribute(lstm_persist, cudaFuncAttributeMaxDynamicSharedMemorySize, SM_TOTAL);
        attr_done = true;
    }

    void* bar1_addr; void* bar2_addr;
    cudaGetSymbolAddress(&bar1_addr, g_bar1);
    cudaGetSymbolAddress(&bar2_addr, g_bar2);
    cudaMemsetAsync(bar1_addr, 0, 8 * 32 * sizeof(unsigned));
    cudaMemsetAsync(bar2_addr, 0, 32 * sizeof(unsigned));

    prep_weights<<<dim3(17, 64), 256>>>(Wk, Wr, bias);
    {
        const size_t ni = (size_t)BSZ * TIN * FDIM;
        prep_inputs<<<(unsigned)((ni + 255) / 256), 256>>>(inputs);
    }

    lstm_persist<<<dim3(BSZ / 64, NGATE / 128), 256, SM_TOTAL>>>(Wd, bd, out);
}